// round 7
// baseline (speedup 1.0000x reference)
#include <cuda_runtime.h>

// Spacial IRNN: 4 directional relu-scans over [B,C,H,W] = [4,64,256,256] fp32.
// out[dir][b][c][h][w], dir: 0=up, 1=right, 2=down, 3=left.
// h_0 = x_edge (raw), h_t = relu(w_c * h_{t-1} + b_c + x_t).
//
// role = blockIdx.x % 5:
//   role 0    -> vertical block: one thread per float2 column pair, up+down
//                interleaved -> 4 independent chains, 8B global ops.
//   role 1..4 -> horizontal block: warp-specialized. Threads 0-127 process
//                "right" on tile A, threads 128-255 "left" on tile B, each on
//                its own named barrier. All tile I/O float4, stride-36 rows.

#define HH 256
#define WW 256
#define BB 4
#define CC 64

constexpr int HW = HH * WW;
constexpr long long DIRSZ = (long long)BB * CC * HH * WW;  // 16,777,216

constexpr int TPB     = 256;
constexpr int VBLOCKS = (BB * CC * WW / 2) / TPB;   // 128
constexpr int HROWS   = 128;
constexpr int HBLOCKS = (BB * CC * HH) / HROWS;     // 512
constexpr int CHUNK   = 32;
constexpr int NCHUNK  = WW / CHUNK;                 // 8
constexpr int STRIDE  = 36;                         // floats; 144B row

__device__ __forceinline__ void bar_group(int id) {
    asm volatile("bar.sync %0, 128;" :: "r"(id) : "memory");
}

__device__ __forceinline__ float2 step2(float w, float2 s, float b, float2 x) {
    float2 r;
    r.x = fmaxf(fmaf(w, s.x, b + x.x), 0.0f);
    r.y = fmaxf(fmaf(w, s.y, b + x.y), 0.0f);
    return r;
}

__global__ void __launch_bounds__(TPB, 5)
irnn_fused_kernel(const float* __restrict__ x,
                  const float* __restrict__ w_up,    const float* __restrict__ b_up,
                  const float* __restrict__ w_right, const float* __restrict__ b_right,
                  const float* __restrict__ w_down,  const float* __restrict__ b_down,
                  const float* __restrict__ w_left,  const float* __restrict__ b_left,
                  float* __restrict__ out)
{
    __shared__ float tiles[2][HROWS * STRIDE];   // [0]=right(A), [1]=left(B)

    const int role = blockIdx.x % 5;
    const int grp  = blockIdx.x / 5;
    const int tid  = threadIdx.x;

    if (role == 0) {
        // ------------- vertical: one thread per (b,c, 2w) float2 column -----
        const int id = grp * TPB + tid;        // 0 .. 32767
        const int w2 = id & 127;               // W/2 = 128
        const int bc = id >> 7;
        const int c  = bc & (CC - 1);
        const int RS = WW / 2;                 // float2 per row

        const float2* xp = ((const float2*)(x + (size_t)bc * HW)) + w2;
        float2* od = ((float2*)(out + 2 * DIRSZ + (size_t)bc * HW)) + w2;  // down
        float2* ou = ((float2*)(out + 0 * DIRSZ + (size_t)bc * HW)) + w2;  // up

        const float wd = w_down[c], bd = b_down[c];
        const float wu = w_up[c],   bu = b_up[c];

        float2 sd = xp[0];
        float2 su = xp[(HH - 1) * RS];
        __stcs(&od[0], sd);
        __stcs(&ou[(HH - 1) * RS], su);

#pragma unroll 4
        for (int h = 1; h < HH; ++h) {
            float2 xd = xp[h * RS];
            float2 xu = xp[(HH - 1 - h) * RS];
            sd = step2(wd, sd, bd, xd);
            su = step2(wu, su, bu, xu);
            __stcs(&od[h * RS], sd);
            __stcs(&ou[(HH - 1 - h) * RS], su);
        }
    } else {
        // ------------------- horizontal: 128 rows, warp-specialized ---------
        const int hb = grp * 4 + (role - 1);     // 0 .. 511
        const int r0 = hb * HROWS;               // first global row
        const int bc = r0 >> 8;                  // uniform within block
        const int c  = bc & (CC - 1);

        const bool isLeft = (tid >= HROWS);
        const int  gt     = tid & (HROWS - 1);   // thread id within group
        const int  barid  = isLeft ? 2 : 1;

        const float* xbase = x + (size_t)r0 * WW;
        float* obase = out + (isLeft ? 3 : 1) * DIRSZ + (size_t)r0 * WW;

        const float wsc = isLeft ? w_left[c] : w_right[c];
        const float bsc = isLeft ? b_left[c] : b_right[c];

        float* tile = &tiles[isLeft ? 1 : 0][0];

        // staging map: f = k*128 + gt ; row = f>>3 ; col4 = f&7
        const int srow  = gt >> 3;               // base row, +16 per k
        const int scol4 = gt & 7;

        float s = 0.0f;
        for (int ch = 0; ch < NCHUNK; ++ch) {
            // right walks chunks forward, left backward
            const int wX = (isLeft ? (NCHUNK - 1 - ch) : ch) * CHUNK;

            // ---- load: LDG.128 -> STS.128 (conflict-free) ----
#pragma unroll
            for (int k = 0; k < 8; ++k) {
                int row = srow + k * 16;
                float4 v = *(const float4*)&xbase[(size_t)row * WW + wX + scol4 * 4];
                *(float4*)&tile[row * STRIDE + scol4 * 4] = v;
            }
            bar_group(barid);

            // ---- scan owned row gt, register-resident, two 16-float halves
            float* tr = &tile[gt * STRIDE];
            if (!isLeft) {
#pragma unroll
                for (int half = 0; half < 2; ++half) {
                    float4 v[4];
#pragma unroll
                    for (int q = 0; q < 4; ++q) v[q] = *(float4*)&tr[(half * 4 + q) * 4];
                    float* a = (float*)v;
#pragma unroll
                    for (int t = 0; t < 16; ++t) {
                        float xv = a[t];
                        if (ch == 0 && half == 0 && t == 0) s = xv;
                        else s = fmaxf(fmaf(wsc, s, bsc + xv), 0.0f);
                        a[t] = s;
                    }
#pragma unroll
                    for (int q = 0; q < 4; ++q) *(float4*)&tr[(half * 4 + q) * 4] = v[q];
                }
            } else {
#pragma unroll
                for (int half = 1; half >= 0; --half) {
                    float4 v[4];
#pragma unroll
                    for (int q = 0; q < 4; ++q) v[q] = *(float4*)&tr[(half * 4 + q) * 4];
                    float* a = (float*)v;
#pragma unroll
                    for (int t = 15; t >= 0; --t) {
                        float xv = a[t];
                        if (ch == 0 && half == 1 && t == 15) s = xv;
                        else s = fmaxf(fmaf(wsc, s, bsc + xv), 0.0f);
                        a[t] = s;
                    }
#pragma unroll
                    for (int q = 0; q < 4; ++q) *(float4*)&tr[(half * 4 + q) * 4] = v[q];
                }
            }
            bar_group(barid);

            // ---- store: LDS.128 -> STG.128 streaming ----
#pragma unroll
            for (int k = 0; k < 8; ++k) {
                int row = srow + k * 16;
                float4 v = *(float4*)&tile[row * STRIDE + scol4 * 4];
                __stcs((float4*)&obase[(size_t)row * WW + wX + scol4 * 4], v);
            }
            bar_group(barid);   // tile reads done before next chunk overwrites
        }
    }
}

extern "C" void kernel_launch(void* const* d_in, const int* in_sizes, int n_in,
                              void* d_out, int out_size)
{
    const float* x       = (const float*)d_in[0];
    const float* w_up    = (const float*)d_in[1];
    const float* w_right = (const float*)d_in[2];
    const float* w_down  = (const float*)d_in[3];
    const float* w_left  = (const float*)d_in[4];
    const float* b_up    = (const float*)d_in[5];
    const float* b_right = (const float*)d_in[6];
    const float* b_down  = (const float*)d_in[7];
    const float* b_left  = (const float*)d_in[8];
    float* out = (float*)d_out;

    int grid = VBLOCKS + HBLOCKS;   // 128 vertical + 512 horizontal = 640
    irnn_fused_kernel<<<grid, TPB>>>(x,
                                     w_up, b_up, w_right, b_right,
                                     w_down, b_down, w_left, b_left,
                                     out);
}

// round 8
// speedup vs baseline: 1.1483x; 1.1483x over previous
#include <cuda_runtime.h>

// Spacial IRNN: 4 directional relu-scans over [B,C,H,W] = [4,64,256,256] fp32.
// out[dir][b][c][h][w], dir: 0=up, 1=right, 2=down, 3=left.
// h_0 = x_edge (raw), h_t = relu(w_c * h_{t-1} + b_c + x_t).
//
// R6 chassis + occupancy push: __launch_bounds__(256,6) (42-reg budget,
// 6 blocks/SM = 48 warps) with the scan's live register window shrunk to
// 8 floats so the serial chain stays spill-free.
// role = blockIdx.x % 3:
//   role 0   -> vertical block (scalar, up+down interleaved chains)
//   role 1,2 -> horizontal block, warp-specialized: threads 0-127 "right" on
//               tile A, threads 128-255 "left" on tile B, own named barriers.

#define HH 256
#define WW 256
#define BB 4
#define CC 64

constexpr int HW = HH * WW;
constexpr long long DIRSZ = (long long)BB * CC * HH * WW;  // 16,777,216

constexpr int TPB     = 256;
constexpr int VBLOCKS = (BB * CC * WW) / TPB;   // 256
constexpr int HROWS   = 128;
constexpr int HBLOCKS = (BB * CC * HH) / HROWS; // 512
constexpr int CHUNK   = 32;
constexpr int NCHUNK  = WW / CHUNK;             // 8
constexpr int STRIDE  = 36;                     // floats; 144B row, 16B-aligned

__device__ __forceinline__ void bar_group(int id) {
    asm volatile("bar.sync %0, 128;" :: "r"(id) : "memory");
}

__global__ void __launch_bounds__(TPB, 6)
irnn_fused_kernel(const float* __restrict__ x,
                  const float* __restrict__ w_up,    const float* __restrict__ b_up,
                  const float* __restrict__ w_right, const float* __restrict__ b_right,
                  const float* __restrict__ w_down,  const float* __restrict__ b_down,
                  const float* __restrict__ w_left,  const float* __restrict__ b_left,
                  float* __restrict__ out)
{
    __shared__ float tiles[2][HROWS * STRIDE];   // [0]=right(A), [1]=left(B)

    const int role = blockIdx.x % 3;
    const int grp  = blockIdx.x / 3;
    const int tid  = threadIdx.x;

    if (role == 0) {
        // ------------------- vertical: one thread per (b,c,w) column --------
        int id = grp * TPB + tid;            // 0 .. B*C*W-1
        int w  = id & (WW - 1);
        int bc = id >> 8;
        int c  = bc & (CC - 1);

        const float* xp = x + (size_t)bc * HW + w;
        float* od = out + 2 * DIRSZ + (size_t)bc * HW + w;  // down
        float* ou = out + 0 * DIRSZ + (size_t)bc * HW + w;  // up

        const float wd = w_down[c], bd = b_down[c];
        const float wu = w_up[c],   bu = b_up[c];

        float sd = xp[0];
        float su = xp[(HH - 1) * WW];
        __stcs(&od[0], sd);
        __stcs(&ou[(HH - 1) * WW], su);

#pragma unroll 8
        for (int h = 1; h < HH; ++h) {
            float xd = xp[h * WW];
            float xu = xp[(HH - 1 - h) * WW];
            sd = fmaxf(fmaf(wd, sd, bd + xd), 0.0f);
            su = fmaxf(fmaf(wu, su, bu + xu), 0.0f);
            __stcs(&od[h * WW], sd);
            __stcs(&ou[(HH - 1 - h) * WW], su);
        }
    } else {
        // ------------------- horizontal: 128 rows, warp-specialized ---------
        const int hb = grp * 2 + (role - 1);     // 0 .. 511
        const int r0 = hb * HROWS;               // first global row
        const int bc = r0 >> 8;                  // uniform within block
        const int c  = bc & (CC - 1);

        const bool isLeft = (tid >= HROWS);
        const int  gt     = tid & (HROWS - 1);   // thread id within group
        const int  barid  = isLeft ? 2 : 1;

        const float* xbase = x + (size_t)r0 * WW;
        float* obase = out + (isLeft ? 3 : 1) * DIRSZ + (size_t)r0 * WW;

        const float wsc = isLeft ? w_left[c] : w_right[c];
        const float bsc = isLeft ? b_left[c] : b_right[c];

        float* tile = &tiles[isLeft ? 1 : 0][0];

        // staging map: f = k*128 + gt ; row = f>>3 ; col4 = f&7
        const int srow  = gt >> 3;               // base row, +16 per k
        const int scol4 = gt & 7;

        float s = 0.0f;
        for (int ch = 0; ch < NCHUNK; ++ch) {
            // right walks chunks forward, left backward
            const int wX = (isLeft ? (NCHUNK - 1 - ch) : ch) * CHUNK;

            // ---- load: LDG.128 -> STS.128 (conflict-free) ----
#pragma unroll
            for (int k = 0; k < 8; ++k) {
                int row = srow + k * 16;
                float4 v = *(const float4*)&xbase[(size_t)row * WW + wX + scol4 * 4];
                *(float4*)&tile[row * STRIDE + scol4 * 4] = v;
            }
            bar_group(barid);

            // ---- scan owned row gt, register-resident in 8-float windows ---
            float* tr = &tile[gt * STRIDE];
            if (!isLeft) {
#pragma unroll
                for (int sb = 0; sb < 4; ++sb) {        // 4 sub-blocks of 8
                    float4 v0 = *(float4*)&tr[sb * 8];
                    float4 v1 = *(float4*)&tr[sb * 8 + 4];
                    float a[8] = {v0.x, v0.y, v0.z, v0.w, v1.x, v1.y, v1.z, v1.w};
#pragma unroll
                    for (int t = 0; t < 8; ++t) {
                        float xv = a[t];
                        if (ch == 0 && sb == 0 && t == 0) s = xv;
                        else s = fmaxf(fmaf(wsc, s, bsc + xv), 0.0f);
                        a[t] = s;
                    }
                    *(float4*)&tr[sb * 8]     = make_float4(a[0], a[1], a[2], a[3]);
                    *(float4*)&tr[sb * 8 + 4] = make_float4(a[4], a[5], a[6], a[7]);
                }
            } else {
#pragma unroll
                for (int sb = 3; sb >= 0; --sb) {
                    float4 v0 = *(float4*)&tr[sb * 8];
                    float4 v1 = *(float4*)&tr[sb * 8 + 4];
                    float a[8] = {v0.x, v0.y, v0.z, v0.w, v1.x, v1.y, v1.z, v1.w};
#pragma unroll
                    for (int t = 7; t >= 0; --t) {
                        float xv = a[t];
                        if (ch == 0 && sb == 3 && t == 7) s = xv;
                        else s = fmaxf(fmaf(wsc, s, bsc + xv), 0.0f);
                        a[t] = s;
                    }
                    *(float4*)&tr[sb * 8]     = make_float4(a[0], a[1], a[2], a[3]);
                    *(float4*)&tr[sb * 8 + 4] = make_float4(a[4], a[5], a[6], a[7]);
                }
            }
            bar_group(barid);

            // ---- store: LDS.128 -> STG.128 streaming ----
#pragma unroll
            for (int k = 0; k < 8; ++k) {
                int row = srow + k * 16;
                float4 v = *(float4*)&tile[row * STRIDE + scol4 * 4];
                __stcs((float4*)&obase[(size_t)row * WW + wX + scol4 * 4], v);
            }
            bar_group(barid);   // tile reads done before next chunk overwrites
        }
    }
}

extern "C" void kernel_launch(void* const* d_in, const int* in_sizes, int n_in,
                              void* d_out, int out_size)
{
    const float* x       = (const float*)d_in[0];
    const float* w_up    = (const float*)d_in[1];
    const float* w_right = (const float*)d_in[2];
    const float* w_down  = (const float*)d_in[3];
    const float* w_left  = (const float*)d_in[4];
    const float* b_up    = (const float*)d_in[5];
    const float* b_right = (const float*)d_in[6];
    const float* b_down  = (const float*)d_in[7];
    const float* b_left  = (const float*)d_in[8];
    float* out = (float*)d_out;

    int grid = VBLOCKS + HBLOCKS;   // 256 vertical + 512 horizontal = 768
    irnn_fused_kernel<<<grid, TPB>>>(x,
                                     w_up, b_up, w_right, b_right,
                                     w_down, b_down, w_left, b_left,
                                     out);
}

// round 9
// speedup vs baseline: 1.1861x; 1.0329x over previous
#include <cuda_runtime.h>

// Spacial IRNN: 4 directional relu-scans over [B,C,H,W] = [4,64,256,256] fp32.
// out[dir][b][c][h][w], dir: 0=up, 1=right, 2=down, 3=left.
// h_0 = x_edge (raw), h_t = relu(w_c * h_{t-1} + b_c + x_t).
//
// Uniform-work grid (1024 blocks, 2KB traffic per thread everywhere):
//   role = bid & 1:
//     0 -> vertical block, ONE direction per block (vb&1: 0=down, 1=up),
//          one thread per column, scalar coalesced I/O, stcs stores.
//     1 -> horizontal block (R6 chassis): warp-specialized, threads 0-127
//          "right" on tile A, 128-255 "left" on tile B, own named barriers,
//          float4 I/O on stride-36 tiles, 8-float register scan windows.

#define HH 256
#define WW 256
#define BB 4
#define CC 64

constexpr int HW = HH * WW;
constexpr long long DIRSZ = (long long)BB * CC * HH * WW;  // 16,777,216

constexpr int TPB     = 256;
constexpr int HROWS   = 128;
constexpr int CHUNK   = 32;
constexpr int NCHUNK  = WW / CHUNK;             // 8
constexpr int STRIDE  = 36;                     // floats; 144B row, 16B-aligned

__device__ __forceinline__ void bar_group(int id) {
    asm volatile("bar.sync %0, 128;" :: "r"(id) : "memory");
}

__global__ void __launch_bounds__(TPB, 6)
irnn_fused_kernel(const float* __restrict__ x,
                  const float* __restrict__ w_up,    const float* __restrict__ b_up,
                  const float* __restrict__ w_right, const float* __restrict__ b_right,
                  const float* __restrict__ w_down,  const float* __restrict__ b_down,
                  const float* __restrict__ w_left,  const float* __restrict__ b_left,
                  float* __restrict__ out)
{
    __shared__ float tiles[2][HROWS * STRIDE];   // [0]=right(A), [1]=left(B)

    const int bid = blockIdx.x;
    const int tid = threadIdx.x;

    if ((bid & 1) == 0) {
        // ---------------- vertical: one direction, one thread per column ----
        const int vb   = bid >> 1;          // 0 .. 511
        const int isUp = vb & 1;            // 0 = down, 1 = up
        const int unit = vb >> 1;           // 0 .. 255

        const int id = unit * TPB + tid;    // 0 .. B*C*W-1
        const int w  = id & (WW - 1);
        const int bc = id >> 8;
        const int c  = bc & (CC - 1);

        const float* xp = x + (size_t)bc * HW + w;

        if (!isUp) {
            float* od = out + 2 * DIRSZ + (size_t)bc * HW + w;   // down
            const float wd = w_down[c], bd = b_down[c];
            float s = xp[0];
            __stcs(&od[0], s);
#pragma unroll 8
            for (int h = 1; h < HH; ++h) {
                float xv = xp[h * WW];
                s = fmaxf(fmaf(wd, s, bd + xv), 0.0f);
                __stcs(&od[h * WW], s);
            }
        } else {
            float* ou = out + 0 * DIRSZ + (size_t)bc * HW + w;   // up
            const float wu = w_up[c], bu = b_up[c];
            float s = xp[(HH - 1) * WW];
            __stcs(&ou[(HH - 1) * WW], s);
#pragma unroll 8
            for (int h = HH - 2; h >= 0; --h) {
                float xv = xp[h * WW];
                s = fmaxf(fmaf(wu, s, bu + xv), 0.0f);
                __stcs(&ou[h * WW], s);
            }
        }
    } else {
        // ------------------- horizontal: 128 rows, warp-specialized ---------
        const int hb = bid >> 1;                 // 0 .. 511
        const int r0 = hb * HROWS;               // first global row
        const int bc = r0 >> 8;                  // uniform within block
        const int c  = bc & (CC - 1);

        const bool isLeft = (tid >= HROWS);
        const int  gt     = tid & (HROWS - 1);   // thread id within group
        const int  barid  = isLeft ? 2 : 1;

        const float* xbase = x + (size_t)r0 * WW;
        float* obase = out + (isLeft ? 3 : 1) * DIRSZ + (size_t)r0 * WW;

        const float wsc = isLeft ? w_left[c] : w_right[c];
        const float bsc = isLeft ? b_left[c] : b_right[c];

        float* tile = &tiles[isLeft ? 1 : 0][0];

        // staging map: f = k*128 + gt ; row = f>>3 ; col4 = f&7
        const int srow  = gt >> 3;               // base row, +16 per k
        const int scol4 = gt & 7;

        float s = 0.0f;
        for (int ch = 0; ch < NCHUNK; ++ch) {
            // right walks chunks forward, left backward
            const int wX = (isLeft ? (NCHUNK - 1 - ch) : ch) * CHUNK;

            // ---- load: LDG.128 -> STS.128 (conflict-free) ----
#pragma unroll
            for (int k = 0; k < 8; ++k) {
                int row = srow + k * 16;
                float4 v = *(const float4*)&xbase[(size_t)row * WW + wX + scol4 * 4];
                *(float4*)&tile[row * STRIDE + scol4 * 4] = v;
            }
            bar_group(barid);

            // ---- scan owned row gt, register-resident in 8-float windows ---
            float* tr = &tile[gt * STRIDE];
            if (!isLeft) {
#pragma unroll
                for (int sb = 0; sb < 4; ++sb) {        // 4 sub-blocks of 8
                    float4 v0 = *(float4*)&tr[sb * 8];
                    float4 v1 = *(float4*)&tr[sb * 8 + 4];
                    float a[8] = {v0.x, v0.y, v0.z, v0.w, v1.x, v1.y, v1.z, v1.w};
#pragma unroll
                    for (int t = 0; t < 8; ++t) {
                        float xv = a[t];
                        if (ch == 0 && sb == 0 && t == 0) s = xv;
                        else s = fmaxf(fmaf(wsc, s, bsc + xv), 0.0f);
                        a[t] = s;
                    }
                    *(float4*)&tr[sb * 8]     = make_float4(a[0], a[1], a[2], a[3]);
                    *(float4*)&tr[sb * 8 + 4] = make_float4(a[4], a[5], a[6], a[7]);
                }
            } else {
#pragma unroll
                for (int sb = 3; sb >= 0; --sb) {
                    float4 v0 = *(float4*)&tr[sb * 8];
                    float4 v1 = *(float4*)&tr[sb * 8 + 4];
                    float a[8] = {v0.x, v0.y, v0.z, v0.w, v1.x, v1.y, v1.z, v1.w};
#pragma unroll
                    for (int t = 7; t >= 0; --t) {
                        float xv = a[t];
                        if (ch == 0 && sb == 3 && t == 7) s = xv;
                        else s = fmaxf(fmaf(wsc, s, bsc + xv), 0.0f);
                        a[t] = s;
                    }
                    *(float4*)&tr[sb * 8]     = make_float4(a[0], a[1], a[2], a[3]);
                    *(float4*)&tr[sb * 8 + 4] = make_float4(a[4], a[5], a[6], a[7]);
                }
            }
            bar_group(barid);

            // ---- store: LDS.128 -> STG.128 streaming ----
#pragma unroll
            for (int k = 0; k < 8; ++k) {
                int row = srow + k * 16;
                float4 v = *(float4*)&tile[row * STRIDE + scol4 * 4];
                __stcs((float4*)&obase[(size_t)row * WW + wX + scol4 * 4], v);
            }
            bar_group(barid);   // tile reads done before next chunk overwrites
        }
    }
}

extern "C" void kernel_launch(void* const* d_in, const int* in_sizes, int n_in,
                              void* d_out, int out_size)
{
    const float* x       = (const float*)d_in[0];
    const float* w_up    = (const float*)d_in[1];
    const float* w_right = (const float*)d_in[2];
    const float* w_down  = (const float*)d_in[3];
    const float* w_left  = (const float*)d_in[4];
    const float* b_up    = (const float*)d_in[5];
    const float* b_right = (const float*)d_in[6];
    const float* b_down  = (const float*)d_in[7];
    const float* b_left  = (const float*)d_in[8];
    float* out = (float*)d_out;

    // 512 vertical (256 down + 256 up) + 512 horizontal, interleaved by parity
    irnn_fused_kernel<<<1024, TPB>>>(x,
                                     w_up, b_up, w_right, b_right,
                                     w_down, b_down, w_left, b_left,
                                     out);
}